// round 13
// baseline (speedup 1.0000x reference)
#include <cuda_runtime.h>
#include <cuda_bf16.h>
#include <math.h>
#include <stdint.h>

// Problem constants
#define Bn   64
#define Vn   36
#define Kn   1024
#define NCn  64
#define Ln   48
#define Hn   9

#define MR    (Bn*Hn*Vn)      // 20736
#define NCOL  (NCn*Ln)        // 3072
#define GMr   (NCn*Bn)        // 4096

// ---------------- scratch ----------------
__device__ float g_logits[(size_t)MR  * NCOL];    // compacted-column logits
__device__ float g_capC  [(size_t)NCOL * Kn];     // column-compacted cap
__device__ int   g_off   [NCn + 1];
__device__ float g_lall  [(size_t)GMr * Hn * Kn];
__device__ float g_Qg    [(size_t)GMr * Kn];
__device__ float g_Kg    [(size_t)GMr * Kn];
__device__ float g_W3o   [(size_t)GMr * Kn];
__device__ float g_carry [(size_t)GMr * Kn];
__device__ __nv_bfloat16 g_Wh [(size_t)3072 * Kn];
__device__ __nv_bfloat16 g_Gh [(size_t)GMr * Kn];
__device__ __nv_bfloat16 g_L2h[(size_t)GMr * Kn];

// ---------------- small helpers ----------------
__device__ __forceinline__ float sigmoidf_(float x) { return 1.f / (1.f + expf(-x)); }

__device__ __forceinline__ float blockReduceSum256(float v) {
    __shared__ float red[8];
    #pragma unroll
    for (int o = 16; o > 0; o >>= 1) v += __shfl_xor_sync(0xffffffffu, v, o);
    int tid = threadIdx.x;
    if ((tid & 31) == 0) red[tid >> 5] = v;
    __syncthreads();
    float s = 0.f;
    int nw = blockDim.x >> 5;
    #pragma unroll
    for (int i = 0; i < 8; i++) if (i < nw) s += red[i];
    __syncthreads();
    return s;
}

// ---------------- mma.sync primitives ----------------
__device__ __forceinline__ uint32_t smem_u32(const void* p) {
    uint32_t a;
    asm("{ .reg .u64 t; cvta.to.shared.u64 t, %1; cvt.u32.u64 %0, t; }" : "=r"(a) : "l"(p));
    return a;
}

__device__ __forceinline__ void ldsm4(uint32_t* r, uint32_t addr) {
    asm volatile("ldmatrix.sync.aligned.m8n8.x4.shared.b16 {%0,%1,%2,%3}, [%4];"
                 : "=r"(r[0]), "=r"(r[1]), "=r"(r[2]), "=r"(r[3]) : "r"(addr));
}

__device__ __forceinline__ void mma_bf16(float* d, const uint32_t* a, const uint32_t* b) {
    asm volatile(
        "mma.sync.aligned.m16n8k16.row.col.f32.bf16.bf16.f32 "
        "{%0,%1,%2,%3}, {%4,%5,%6,%7}, {%8,%9}, {%0,%1,%2,%3};"
        : "+f"(d[0]), "+f"(d[1]), "+f"(d[2]), "+f"(d[3])
        : "r"(a[0]), "r"(a[1]), "r"(a[2]), "r"(a[3]), "r"(b[0]), "r"(b[1]));
}

__device__ __forceinline__ void split_store(float4 v, char* hip, char* lop) {
    __nv_bfloat16 hx = __float2bfloat16(v.x);
    __nv_bfloat16 hy = __float2bfloat16(v.y);
    __nv_bfloat16 hz = __float2bfloat16(v.z);
    __nv_bfloat16 hw = __float2bfloat16(v.w);
    __nv_bfloat16 lx = __float2bfloat16(v.x - __bfloat162float(hx));
    __nv_bfloat16 ly = __float2bfloat16(v.y - __bfloat162float(hy));
    __nv_bfloat16 lz = __float2bfloat16(v.z - __bfloat162float(hz));
    __nv_bfloat16 lw = __float2bfloat16(v.w - __bfloat162float(hw));
    __nv_bfloat162 h01 = __halves2bfloat162(hx, hy);
    __nv_bfloat162 h23 = __halves2bfloat162(hz, hw);
    __nv_bfloat162 l01 = __halves2bfloat162(lx, ly);
    __nv_bfloat162 l23 = __halves2bfloat162(lz, lw);
    *(uint2*)hip = make_uint2(*(unsigned*)&h01, *(unsigned*)&h23);
    *(uint2*)lop = make_uint2(*(unsigned*)&l01, *(unsigned*)&l23);
}

// hi-only bf16 store of fp32x4
__device__ __forceinline__ void hi_store(float4 v, char* hip) {
    __nv_bfloat162 h01 = __halves2bfloat162(__float2bfloat16(v.x), __float2bfloat16(v.y));
    __nv_bfloat162 h23 = __halves2bfloat162(__float2bfloat16(v.z), __float2bfloat16(v.w));
    *(uint2*)hip = make_uint2(*(unsigned*)&h01, *(unsigned*)&h23);
}

__device__ __forceinline__ void split1(float x, __nv_bfloat16& hi, __nv_bfloat16& lo) {
    hi = __float2bfloat16(x);
    lo = __float2bfloat16(x - __bfloat162float(hi));
}

// ---------------- compaction prep ----------------
__global__ void k_prefix(const int* __restrict__ lens) {
    if (threadIdx.x == 0) {
        int a = 0;
        for (int j = 0; j < NCn; j++) { g_off[j] = a; a += lens[j]; }
        g_off[NCn] = a;
    }
}
__global__ void k_zeroC() {
    ((float4*)g_capC)[(size_t)blockIdx.x * 256 + threadIdx.x] = make_float4(0.f, 0.f, 0.f, 0.f);
}
__global__ void k_fillC(const float* __restrict__ cap, const int* __restrict__ lens) {
    int j = blockIdx.x, q = blockIdx.y;
    if (q >= lens[j]) return;
    int dst = g_off[j] + q;
    ((float4*)&g_capC[(size_t)dst * Kn])[threadIdx.x] =
        ((const float4*)&cap[(size_t)(j * Ln + q) * Kn])[threadIdx.x];
}

// ================= logits GEMM: imgH fused, 3-term split-bf16, compacted columns ====
#define ROWP    40
#define MAT_B   (128 * ROWP * 2)
#define STG_B   (4 * MAT_B)
#define GEMM_DSMEM (2 * STG_B)
#define NCHUNK  (Kn / 32)

__global__ void __launch_bounds__(256, 1)
logits_gemm(const float* __restrict__ A, const float* __restrict__ B, float* __restrict__ C,
            const float* __restrict__ hmat) {
    if (blockIdx.x * 128 >= g_off[NCn]) return;
    extern __shared__ char smem[];
    const uint32_t sbase = smem_u32(smem);
    const int tid  = threadIdx.x;
    const int lane = tid & 31;
    const int wid  = tid >> 5;
    const int wm   = wid >> 2;
    const int wc   = wid & 3;

    const int m0 = blockIdx.y * 128;
    const int n0 = blockIdx.x * 128;

    const float* ap[4]; const float* hp[4]; const float* bp[4];
    uint32_t soff[4];
    #pragma unroll
    for (int i = 0; i < 4; i++) {
        int idx = tid + i * 256;
        int r   = idx >> 3;
        int c4  = idx & 7;
        soff[i] = (uint32_t)(r * ROWP + c4 * 4);
        int m = m0 + r;
        int v = m % Vn;
        int h = (m / Vn) % Hn;
        int b = m / (Vn * Hn);
        ap[i] = A    + (size_t)(b * Vn + v) * Kn + c4 * 4;
        hp[i] = hmat + (size_t)h * Kn            + c4 * 4;
        bp[i] = B + (size_t)(n0 + r) * Kn + c4 * 4;
    }

    float acc[4][4][4];
    #pragma unroll
    for (int f = 0; f < 4; f++)
        #pragma unroll
        for (int g = 0; g < 4; g++)
            #pragma unroll
            for (int e = 0; e < 4; e++) acc[f][g][e] = 0.f;

    const int l15 = lane & 15;
    const int lhi = lane >> 4;
    const uint32_t afr = (uint32_t)((wm * 64 + l15) * 80 + lhi * 16);
    const uint32_t bfr = (uint32_t)((wc * 32 + l15) * 80 + lhi * 16);

    {
        char* st = smem;
        #pragma unroll
        for (int i = 0; i < 4; i++) {
            float4 va = *(const float4*)ap[i];
            float4 h4 = *(const float4*)hp[i];
            va.x *= h4.x; va.y *= h4.y; va.z *= h4.z; va.w *= h4.w;
            split_store(va, st + soff[i]*2, st + MAT_B + soff[i]*2);
            float4 vb = *(const float4*)bp[i];
            split_store(vb, st + 2*MAT_B + soff[i]*2, st + 3*MAT_B + soff[i]*2);
        }
    }

    for (int c = 0; c < NCHUNK; c++) {
        __syncthreads();

        float4 va[4], vb[4], h4[4];
        const bool more = (c + 1 < NCHUNK);
        if (more) {
            int k0 = (c + 1) * 32;
            #pragma unroll
            for (int i = 0; i < 4; i++) {
                va[i] = *(const float4*)(ap[i] + k0);
                h4[i] = *(const float4*)(hp[i] + k0);
                vb[i] = *(const float4*)(bp[i] + k0);
            }
        }

        const uint32_t bufb = sbase + (uint32_t)((c & 1) * STG_B);
        #pragma unroll
        for (int kk = 0; kk < 2; kk++) {
            const uint32_t ko = (uint32_t)(kk * 32);
            uint32_t ah[4][4], al[4][4];
            #pragma unroll
            for (int f = 0; f < 4; f++) {
                uint32_t ao = afr + (uint32_t)(f * 16 * 80) + ko;
                ldsm4(ah[f], bufb + ao);
                ldsm4(al[f], bufb + MAT_B + ao);
            }
            uint32_t bh[4][2], bl[4][2];
            #pragma unroll
            for (int p = 0; p < 2; p++) {
                uint32_t bo = bfr + (uint32_t)(p * 16 * 80) + ko;
                uint32_t t[4];
                ldsm4(t, bufb + 2*MAT_B + bo);
                bh[p*2+0][0] = t[0]; bh[p*2+0][1] = t[2];
                bh[p*2+1][0] = t[1]; bh[p*2+1][1] = t[3];
                ldsm4(t, bufb + 3*MAT_B + bo);
                bl[p*2+0][0] = t[0]; bl[p*2+0][1] = t[2];
                bl[p*2+1][0] = t[1]; bl[p*2+1][1] = t[3];
            }
            #pragma unroll
            for (int f = 0; f < 4; f++)
                #pragma unroll
                for (int g = 0; g < 4; g++) {
                    mma_bf16(acc[f][g], ah[f], bh[g]);
                    mma_bf16(acc[f][g], ah[f], bl[g]);
                    mma_bf16(acc[f][g], al[f], bh[g]);
                }
        }

        if (more) {
            char* st = smem + ((c + 1) & 1) * STG_B;
            #pragma unroll
            for (int i = 0; i < 4; i++) {
                float4 v = va[i];
                v.x *= h4[i].x; v.y *= h4[i].y; v.z *= h4[i].z; v.w *= h4[i].w;
                split_store(v, st + soff[i]*2, st + MAT_B + soff[i]*2);
                split_store(vb[i], st + 2*MAT_B + soff[i]*2, st + 3*MAT_B + soff[i]*2);
            }
        }
    }

    const int rbase = m0 + wm * 64 + (lane >> 2);
    const int cbase = n0 + wc * 32 + (lane & 3) * 2;
    #pragma unroll
    for (int f = 0; f < 4; f++) {
        int r = rbase + f * 16;
        #pragma unroll
        for (int g = 0; g < 4; g++) {
            int cc = cbase + g * 8;
            *(float2*)&C[(size_t)r * NCOL + cc]       = make_float2(acc[f][g][0], acc[f][g][1]);
            *(float2*)&C[(size_t)(r + 8) * NCOL + cc] = make_float2(acc[f][g][2], acc[f][g][3]);
        }
    }
}

// ================= gated-phase GEMM (1-term, pure bf16) =================
#define PMAT_B  (128 * ROWP * 2)
#define PSTG_B  (2 * PMAT_B)
#define PGEMM_DSMEM (2 * PSTG_B)

__global__ void __launch_bounds__(256, 1)
gated_gemm(const __nv_bfloat16* __restrict__ Gh, const __nv_bfloat16* __restrict__ L2h,
           const __nv_bfloat16* __restrict__ Wh,
           float* __restrict__ Cq, float* __restrict__ Ck, float* __restrict__ Cw) {
    extern __shared__ char smem[];
    const uint32_t sbase = smem_u32(smem);
    const int tid  = threadIdx.x;
    const int lane = tid & 31;
    const int wid  = tid >> 5;
    const int wm   = wid >> 2;
    const int wc   = wid & 3;

    const int nx = blockIdx.x;
    const int m0 = blockIdx.y * 128;

    const __nv_bfloat16* Ah = (nx < 16) ? Gh : L2h;
    const __nv_bfloat16* Bp = Wh + (size_t)(nx * 128) * Kn;
    float* C; int n0c;
    if (nx < 8)       { C = Cq; n0c = nx * 128; }
    else if (nx < 16) { C = Ck; n0c = (nx - 8) * 128; }
    else              { C = Cw; n0c = (nx - 16) * 128; }

    const __nv_bfloat16* ahp[2]; const __nv_bfloat16* bhp[2];
    uint32_t so[2];
    #pragma unroll
    for (int i = 0; i < 2; i++) {
        int idx = tid + i * 256;
        int r = idx >> 2, c8 = idx & 3;
        so[i] = (uint32_t)(r * ROWP + c8 * 8) * 2;
        ahp[i] = Ah + (size_t)(m0 + r) * Kn + c8 * 8;
        bhp[i] = Bp + (size_t)r * Kn + c8 * 8;
    }

    float acc[4][4][4];
    #pragma unroll
    for (int f = 0; f < 4; f++)
        #pragma unroll
        for (int g = 0; g < 4; g++)
            #pragma unroll
            for (int e = 0; e < 4; e++) acc[f][g][e] = 0.f;

    const int l15 = lane & 15;
    const int lhi = lane >> 4;
    const uint32_t afr = (uint32_t)((wm * 64 + l15) * 80 + lhi * 16);
    const uint32_t bfr = (uint32_t)((wc * 32 + l15) * 80 + lhi * 16);

    {
        char* st = smem;
        #pragma unroll
        for (int i = 0; i < 2; i++) {
            *(uint4*)(st + so[i])          = *(const uint4*)ahp[i];
            *(uint4*)(st + PMAT_B + so[i]) = *(const uint4*)bhp[i];
        }
    }

    for (int c = 0; c < NCHUNK; c++) {
        __syncthreads();

        uint4 va[2], vb[2];
        const bool more = (c + 1 < NCHUNK);
        if (more) {
            int k0 = (c + 1) * 32;
            #pragma unroll
            for (int i = 0; i < 2; i++) {
                va[i] = *(const uint4*)(ahp[i] + k0);
                vb[i] = *(const uint4*)(bhp[i] + k0);
            }
        }

        const uint32_t bufb = sbase + (uint32_t)((c & 1) * PSTG_B);
        #pragma unroll
        for (int kk = 0; kk < 2; kk++) {
            const uint32_t ko = (uint32_t)(kk * 32);
            uint32_t ah[4][4];
            #pragma unroll
            for (int f = 0; f < 4; f++) {
                uint32_t ao = afr + (uint32_t)(f * 16 * 80) + ko;
                ldsm4(ah[f], bufb + ao);
            }
            uint32_t bh[4][2];
            #pragma unroll
            for (int p = 0; p < 2; p++) {
                uint32_t bo = bfr + (uint32_t)(p * 16 * 80) + ko;
                uint32_t t[4];
                ldsm4(t, bufb + PMAT_B + bo);
                bh[p*2+0][0] = t[0]; bh[p*2+0][1] = t[2];
                bh[p*2+1][0] = t[1]; bh[p*2+1][1] = t[3];
            }
            #pragma unroll
            for (int f = 0; f < 4; f++)
                #pragma unroll
                for (int g = 0; g < 4; g++)
                    mma_bf16(acc[f][g], ah[f], bh[g]);
        }

        if (more) {
            char* st = smem + ((c + 1) & 1) * PSTG_B;
            #pragma unroll
            for (int i = 0; i < 2; i++) {
                *(uint4*)(st + so[i])          = va[i];
                *(uint4*)(st + PMAT_B + so[i]) = vb[i];
            }
        }
    }

    const int rbase = m0 + wm * 64 + (lane >> 2);
    const int cbase = n0c + wc * 32 + (lane & 3) * 2;
    #pragma unroll
    for (int f = 0; f < 4; f++) {
        int r = rbase + f * 16;
        #pragma unroll
        for (int g = 0; g < 4; g++) {
            int cc = cbase + g * 8;
            *(float2*)&C[(size_t)r * Kn + cc]       = make_float2(acc[f][g][0], acc[f][g][1]);
            *(float2*)&C[(size_t)(r + 8) * Kn + cc] = make_float2(acc[f][g][2], acc[f][g][3]);
        }
    }
}

// ---------------- weight pre-split ----------------
__global__ void k_split_w(const float* __restrict__ W1, const float* __restrict__ W2,
                          const float* __restrict__ W3) {
    int idx = blockIdx.x * 256 + threadIdx.x;
    int r  = idx >> 8;
    int c4 = (idx & 255) * 4;
    const float* src = (r < 1024) ? W1 + (size_t)r * Kn
                     : (r < 2048) ? W2 + (size_t)(r - 1024) * Kn
                                  : W3 + (size_t)(r - 2048) * Kn;
    float4 v = *(const float4*)&src[c4];
    hi_store(v, (char*)&g_Wh[(size_t)r * Kn + c4]);
}

// ================= l_all: fused softmax, 3-role pipelined tensor cores ============
// 8 mma warps (21 mtiles, uneven {3,3,3,3,3,2,2,2}), 6 reduce warps, 2 loader warps.
// k-chunk 32. M1 double-buffered (pitch 44 f32), cap double-buffered, img triple.
#define LPROW      56                       // p / capT row pitch in bf16 (112 B)
#define L_OFF_PH   0                        // 336*56*2 = 37632
#define L_OFF_PL   37632
#define L_OFF_CH   75264                    // 2 bufs x 32*56*2 = 2x3584
#define L_OFF_CL   82432                    // 2 bufs x 3584
#define L_OFF_IMG  89600                    // 3 bufs x 36*32*4 = 3x4608
#define L_OFF_M1   103424                   // 2 bufs x 336*44*4 = 2x59136
#define L_OFF_MX   221696                   // invs[9]
#define LALL_SMEM  221824
#define NC32       (Kn / 32)                // 32 chunks

__global__ void __launch_bounds__(512, 1)
k_lall_tc(const float* __restrict__ img, const float* __restrict__ cap,
          const int* __restrict__ lens) {
    extern __shared__ char sm[];
    const uint32_t sb = smem_u32(sm);
    __nv_bfloat16* pH = (__nv_bfloat16*)(sm + L_OFF_PH);
    __nv_bfloat16* pL = (__nv_bfloat16*)(sm + L_OFF_PL);
    float*       pRaw = (float*)(sm + L_OFF_M1);     // prologue alias (324*48*4=62208 < 118272)
    float*       invs = (float*)(sm + L_OFF_MX);

    const int bid = blockIdx.x;           // j*Bn + b
    const int b = bid % Bn;
    const int j = bid / Bn;
    const int tid  = threadIdx.x;
    const int lane = tid & 31;
    const int wid  = tid >> 5;
    const int l15  = lane & 15;
    const int lhi  = lane >> 4;
    const int len  = lens[j];
    const int off  = g_off[j];
    const int nks  = (len + 15) >> 4;
    const float NEG = -3.402823466e38f;

    // ---- prologue pass 1: raw logits into pRaw ----
    for (int e = tid; e < 324 * 48; e += 512) {
        int m = e / 48, q = e - m * 48;
        int h = m / 36, v = m - h * 36;
        float x = NEG;
        if (q < len)
            x = g_logits[(size_t)((b * Hn + h) * Vn + v) * NCOL + off + q];
        pRaw[e] = x;
    }
    __syncthreads();

    // ---- prologue pass 2: warp-per-head softmax ----
    if (wid < Hn) {
        const int h = wid;
        float mx = NEG;
        for (int e = lane; e < 1728; e += 32) mx = fmaxf(mx, pRaw[h * 1728 + e]);
        #pragma unroll
        for (int o = 16; o > 0; o >>= 1) mx = fmaxf(mx, __shfl_xor_sync(0xffffffffu, mx, o));
        float s = 0.f;
        for (int e = lane; e < 1728; e += 32) {
            float x = expf(pRaw[h * 1728 + e] - mx);
            pRaw[h * 1728 + e] = x;
            s += x;
        }
        #pragma unroll
        for (int o = 16; o > 0; o >>= 1) s += __shfl_xor_sync(0xffffffffu, s, o);
        if (lane == 0) invs[h] = 1.f / s;
    }
    __syncthreads();

    // ---- prologue pass 3: normalized p -> split bf16 ----
    for (int e = tid; e < 336 * 48; e += 512) {
        int m = e / 48, q = e - m * 48;
        float x = 0.f;
        if (m < 324) x = pRaw[m * 48 + q] * invs[m / 36];
        __nv_bfloat16 hi, lo; split1(x, hi, lo);
        pH[m * LPROW + q] = hi;
        pL[m * LPROW + q] = lo;
    }
    __syncthreads();   // pRaw (= M1 buf region) fully consumed before chunk 0 mma writes

    // ---- chunk 0 cap/img into buffer 0 (all threads) ----
    {
        __nv_bfloat16* cH0 = (__nv_bfloat16*)(sm + L_OFF_CH);
        __nv_bfloat16* cL0 = (__nv_bfloat16*)(sm + L_OFF_CL);
        float*         im0 = (float*)(sm + L_OFF_IMG);
        for (int e = tid; e < 32 * 48; e += 512) {
            int k = e & 31, q = e >> 5;
            float x = cap[(size_t)(j * Ln + q) * Kn + k];
            __nv_bfloat16 hi, lo; split1(x, hi, lo);
            cH0[k * LPROW + q] = hi;
            cL0[k * LPROW + q] = lo;
        }
        for (int e = tid; e < 36 * 32; e += 512) {
            int k = e & 31, v = e >> 5;
            im0[v * 32 + k] = img[(size_t)(b * Vn + v) * Kn + k];
        }
    }

    // mtile assignment for the 8 mma warps
    const int MT0[8] = {0, 3, 6, 9, 12, 15, 17, 19};
    const int CNT[8] = {3, 3, 3, 3, 3, 2, 2, 2};

    // ---- pipelined main loop: mma(t) | reduce(t-1) | load(t+1) ----
    for (int t = 0; t <= NC32; t++) {
        __syncthreads();

        if (wid < 8) {
            if (t < NC32) {
                const int mt0 = MT0[wid], cnt = CNT[wid];
                const uint32_t cbuf = (uint32_t)((t & 1) * 3584);
                float* M1w = (float*)(sm + L_OFF_M1 + (t & 1) * 59136);

                float acc[3][4][4];
                #pragma unroll
                for (int i = 0; i < 3; i++)
                    #pragma unroll
                    for (int nt = 0; nt < 4; nt++)
                        #pragma unroll
                        for (int e = 0; e < 4; e++) acc[i][nt][e] = 0.f;

                #pragma unroll 3
                for (int ks = 0; ks < nks; ks++) {
                    uint32_t bh[4][2], bl[4][2];
                    #pragma unroll
                    for (int p2 = 0; p2 < 2; p2++) {
                        uint32_t bo = (uint32_t)((p2 * 16 + l15) * 112 + lhi * 16 + ks * 32);
                        uint32_t tt[4];
                        ldsm4(tt, sb + L_OFF_CH + cbuf + bo);
                        bh[p2*2+0][0] = tt[0]; bh[p2*2+0][1] = tt[2];
                        bh[p2*2+1][0] = tt[1]; bh[p2*2+1][1] = tt[3];
                        ldsm4(tt, sb + L_OFF_CL + cbuf + bo);
                        bl[p2*2+0][0] = tt[0]; bl[p2*2+0][1] = tt[2];
                        bl[p2*2+1][0] = tt[1]; bl[p2*2+1][1] = tt[3];
                    }
                    #pragma unroll
                    for (int i = 0; i < 3; i++) {
                        if (i < cnt) {
                            uint32_t ao = (uint32_t)(((mt0 + i) * 16 + l15) * 112 + lhi * 16 + ks * 32);
                            uint32_t ah[4], al[4];
                            ldsm4(ah, sb + L_OFF_PH + ao);
                            ldsm4(al, sb + L_OFF_PL + ao);
                            #pragma unroll
                            for (int nt = 0; nt < 4; nt++) {
                                mma_bf16(acc[i][nt], ah, bh[nt]);
                                mma_bf16(acc[i][nt], ah, bl[nt]);
                                mma_bf16(acc[i][nt], al, bh[nt]);
                            }
                        }
                    }
                }
                #pragma unroll
                for (int i = 0; i < 3; i++) {
                    if (i < cnt) {
                        int r = (mt0 + i) * 16 + (lane >> 2);
                        #pragma unroll
                        for (int nt = 0; nt < 4; nt++) {
                            int c = nt * 8 + (lane & 3) * 2;
                            *(float2*)&M1w[r * 44 + c]       = make_float2(acc[i][nt][0], acc[i][nt][1]);
                            *(float2*)&M1w[(r + 8) * 44 + c] = make_float2(acc[i][nt][2], acc[i][nt][3]);
                        }
                    }
                }
            }
        } else if (wid < 14) {
            if (t >= 1) {
                // reduce chunk t-1: l[h, k] = sum_v M1[(h*36+v), k] * img[v, k]
                const float* M1r = (const float*)(sm + L_OFF_M1 + ((t - 1) & 1) * 59136);
                const float* imC = (const float*)(sm + L_OFF_IMG + ((t - 1) % 3) * 4608);
                const int rt = tid - 256;           // 0..191
                const int k0 = (t - 1) * 32;
                for (int e = rt; e < Hn * 32; e += 192) {
                    int h = e >> 5, kt = e & 31;
                    float a = 0.f;
                    #pragma unroll
                    for (int v = 0; v < Vn; v++)
                        a += M1r[(h * Vn + v) * 44 + kt] * imC[v * 32 + kt];
                    g_lall[(size_t)(bid * Hn + h) * Kn + k0 + kt] = a;
                }
            }
        } else {
            if (t + 1 < NC32) {
                // load chunk t+1
                const int lt = tid - 448;           // 0..63
                const int kn0 = (t + 1) * 32;
                __nv_bfloat16* cHB = (__nv_bfloat16*)(sm + L_OFF_CH + ((t + 1) & 1) * 3584);
                __nv_bfloat16* cLB = (__nv_bfloat16*)(sm + L_OFF_CL + ((t + 1) & 1) * 3584);
                float*         imB = (float*)(sm + L_OFF_IMG + ((t + 1) % 3) * 4608);
                for (int e = lt; e < 32 * 48; e += 64) {
                    int k = e & 31, q = e >> 5;
                    float x = cap[(size_t)(j * Ln + q) * Kn + kn0 + k];
                    __nv_bfloat16 hi, lo; split1(x, hi, lo);
                    cHB[k * LPROW + q] = hi;
                    cLB[k * LPROW + q] = lo;
                }
                for (int e = lt; e < 36 * 32; e += 64) {
                    int k = e & 31, v = e >> 5;
                    imB[v * 32 + k] = img[(size_t)(b * Vn + v) * Kn + kn0 + k];
                }
            }
        }
    }
}

// ---------------- gated elementwise ----------------
__global__ void k_e1(const float* __restrict__ l1, int lda1,
                     const float* __restrict__ l2, int lda2) {
    int idx = blockIdx.x * blockDim.x + threadIdx.x;
    int m  = idx / (Kn / 4);
    int k4 = (idx % (Kn / 4)) * 4;
    float4 a = *(const float4*)&l1[(size_t)m * lda1 + k4];
    float4 c = *(const float4*)&l2[(size_t)m * lda2 + k4];
    float4 g = make_float4(a.x + tanhf(c.x), a.y + tanhf(c.y),
                           a.z + tanhf(c.z), a.w + tanhf(c.w));
    size_t off = (size_t)m * Kn + k4;
    hi_store(g, (char*)(g_Gh + off));
    hi_store(c, (char*)(g_L2h + off));
}

__global__ void __launch_bounds__(256) k_e2f(const float* __restrict__ l1, int lda1,
                                             const float* __restrict__ l2, int lda2,
                                             const float* __restrict__ b1,
                                             const float* __restrict__ b2,
                                             const float* __restrict__ b3,
                                             const float* __restrict__ l1n, int last) {
    const int m  = blockIdx.x;
    const int k4 = threadIdx.x * 4;
    float4 a1 = *(const float4*)&l1[(size_t)m * lda1 + k4];
    float4 a2 = *(const float4*)&l2[(size_t)m * lda2 + k4];
    float4 qv = *(const float4*)&g_Qg [(size_t)m * Kn + k4];
    float4 kv = *(const float4*)&g_Kg [(size_t)m * Kn + k4];
    float4 wv = *(const float4*)&g_W3o[(size_t)m * Kn + k4];
    float4 vb1 = *(const float4*)&b1[k4];
    float4 vb2 = *(const float4*)&b2[k4];
    float4 vb3 = *(const float4*)&b3[k4];

    float4 x;
    x.x = tanhf(a1.x) * sigmoidf_(qv.x + vb1.x) + a1.x + (wv.x + vb3.x) * sigmoidf_(kv.x + vb2.x) + a2.x;
    x.y = tanhf(a1.y) * sigmoidf_(qv.y + vb1.y) + a1.y + (wv.y + vb3.y) * sigmoidf_(kv.y + vb2.y) + a2.y;
    x.z = tanhf(a1.z) * sigmoidf_(qv.z + vb1.z) + a1.z + (wv.z + vb3.z) * sigmoidf_(kv.z + vb2.z) + a2.z;
    x.w = tanhf(a1.w) * sigmoidf_(qv.w + vb1.w) + a1.w + (wv.w + vb3.w) * sigmoidf_(kv.w + vb2.w) + a2.w;

    float ss = x.x * x.x + x.y * x.y + x.z * x.z + x.w * x.w;
    float tot = blockReduceSum256(ss);
    float inv = 1.f / (sqrtf(tot) + 1e-8f);
    float4 o = make_float4(x.x * inv, x.y * inv, x.z * inv, x.w * inv);
    size_t off = (size_t)m * Kn + k4;
    *(float4*)&g_carry[off] = o;

    if (!last) {
        hi_store(o, (char*)(g_L2h + off));
        float4 a = *(const float4*)&l1n[(size_t)m * (Hn * Kn) + k4];
        float4 g = make_float4(a.x + tanhf(o.x), a.y + tanhf(o.y),
                               a.z + tanhf(o.z), a.w + tanhf(o.w));
        hi_store(g, (char*)(g_Gh + off));
    }
}

// ---------------- final ----------------
__global__ void k_final(float* __restrict__ out) {
    const int m = blockIdx.x;
    const int b = m % Bn;
    const int j = m / Bn;
    float s = 0.f;
    for (int k = threadIdx.x; k < Kn; k += 256) s += g_carry[(size_t)m * Kn + k];
    float tot = blockReduceSum256(s);
    if (threadIdx.x == 0) out[b * NCn + j] = tot;
}

// ---------------- launcher ----------------
extern "C" void kernel_launch(void* const* d_in, const int* in_sizes, int n_in,
                              void* d_out, int out_size) {
    const float* img  = (const float*)d_in[0];
    const float* cap  = (const float*)d_in[1];
    const int*   lens = (const int*)  d_in[2];
    const float* hmat = (const float*)d_in[3];
    /* d_in[4] = h_bias: softmax-invariant, unused */
    const float* W1 = (const float*)d_in[5];
    const float* b1 = (const float*)d_in[6];
    const float* W2 = (const float*)d_in[7];
    const float* b2 = (const float*)d_in[8];
    const float* W3 = (const float*)d_in[9];
    const float* b3 = (const float*)d_in[10];
    float* out = (float*)d_out;

    cudaFuncSetAttribute(k_lall_tc, cudaFuncAttributeMaxDynamicSharedMemorySize, LALL_SMEM);
    cudaFuncSetAttribute(logits_gemm, cudaFuncAttributeMaxDynamicSharedMemorySize, GEMM_DSMEM);
    cudaFuncSetAttribute(gated_gemm, cudaFuncAttributeMaxDynamicSharedMemorySize, PGEMM_DSMEM);

    float *pLall, *pQ, *pKg, *pW3o, *pCar, *pLog, *pCapC;
    __nv_bfloat16 *pWh, *pGh, *pL2h;
    cudaGetSymbolAddress((void**)&pLog,  g_logits);
    cudaGetSymbolAddress((void**)&pCapC, g_capC);
    cudaGetSymbolAddress((void**)&pLall, g_lall);
    cudaGetSymbolAddress((void**)&pQ,    g_Qg);
    cudaGetSymbolAddress((void**)&pKg,   g_Kg);
    cudaGetSymbolAddress((void**)&pW3o,  g_W3o);
    cudaGetSymbolAddress((void**)&pCar,  g_carry);
    cudaGetSymbolAddress((void**)&pWh,   g_Wh);
    cudaGetSymbolAddress((void**)&pGh,   g_Gh);
    cudaGetSymbolAddress((void**)&pL2h,  g_L2h);

    k_split_w<<<3072, 256>>>(W1, W2, W3);

    // Phase 0: compaction prep
    k_prefix<<<1, 32>>>(lens);
    k_zeroC<<<NCOL, 256>>>();
    k_fillC<<<dim3(NCn, Ln), 256>>>(cap, lens);

    // Phase 1: logits GEMM over compacted active columns
    logits_gemm<<<dim3(NCOL / 128, MR / 128), 256, GEMM_DSMEM>>>(img, pCapC, pLog, hmat);

    // Phase 2: attended features l_all (pipelined warp-specialized tensor cores)
    k_lall_tc<<<NCn * Bn, 512, LALL_SMEM>>>(img, cap, lens);

    // Phase 3: 8 gated steps (1-term bf16 GEMM)
    k_e1<<<GMr * (Kn / 4) / 256, 256>>>(pLall, Hn * Kn, pLall + Kn, Hn * Kn);
    for (int s = 0; s < 8; s++) {
        int hs = (s == 0) ? 0 : (s + 1);
        const float* l1 = pLall + (size_t)hs * Kn;  int lda1 = Hn * Kn;
        const float* l2; int lda2;
        if (s == 0) { l2 = pLall + Kn; lda2 = Hn * Kn; }
        else        { l2 = pCar;       lda2 = Kn; }
        const float* l1n = (s < 7) ? (pLall + (size_t)(s + 2) * Kn) : pLall;

        gated_gemm<<<dim3(24, GMr / 128), 256, PGEMM_DSMEM>>>(
            pGh, pL2h, pWh, pQ, pKg, pW3o);
        k_e2f<<<GMr, 256>>>(l1, lda1, l2, lda2, b1, b2, b3, l1n, s == 7);
    }

    // Phase 4: feature-sum -> (B, Nc)
    k_final<<<GMr, 256>>>(out);
}

// round 14
// speedup vs baseline: 1.5143x; 1.5143x over previous
#include <cuda_runtime.h>
#include <cuda_bf16.h>
#include <math.h>
#include <stdint.h>

// Problem constants
#define Bn   64
#define Vn   36
#define Kn   1024
#define NCn  64
#define Ln   48
#define Hn   9

#define MR    (Bn*Hn*Vn)      // 20736
#define NCOL  (NCn*Ln)        // 3072
#define GMr   (NCn*Bn)        // 4096

// ---------------- scratch ----------------
__device__ float g_logits[(size_t)MR  * NCOL];    // compacted-column logits
__device__ float g_capC  [(size_t)NCOL * Kn];     // column-compacted cap
__device__ int   g_off   [NCn + 1];
__device__ float g_lall  [(size_t)GMr * Hn * Kn];
__device__ float g_Qg    [(size_t)GMr * Kn];
__device__ float g_Kg    [(size_t)GMr * Kn];
__device__ float g_W3o   [(size_t)GMr * Kn];
__device__ float g_carry [(size_t)GMr * Kn];
__device__ __nv_bfloat16 g_Wh [(size_t)3072 * Kn];
__device__ __nv_bfloat16 g_Gh [(size_t)GMr * Kn];
__device__ __nv_bfloat16 g_L2h[(size_t)GMr * Kn];

// ---------------- small helpers ----------------
__device__ __forceinline__ float sigmoidf_(float x) { return 1.f / (1.f + expf(-x)); }

__device__ __forceinline__ float blockReduceSum256(float v) {
    __shared__ float red[8];
    #pragma unroll
    for (int o = 16; o > 0; o >>= 1) v += __shfl_xor_sync(0xffffffffu, v, o);
    int tid = threadIdx.x;
    if ((tid & 31) == 0) red[tid >> 5] = v;
    __syncthreads();
    float s = 0.f;
    int nw = blockDim.x >> 5;
    #pragma unroll
    for (int i = 0; i < 8; i++) if (i < nw) s += red[i];
    __syncthreads();
    return s;
}

// ---------------- mma.sync primitives ----------------
__device__ __forceinline__ uint32_t smem_u32(const void* p) {
    uint32_t a;
    asm("{ .reg .u64 t; cvta.to.shared.u64 t, %1; cvt.u32.u64 %0, t; }" : "=r"(a) : "l"(p));
    return a;
}

__device__ __forceinline__ void ldsm4(uint32_t* r, uint32_t addr) {
    asm volatile("ldmatrix.sync.aligned.m8n8.x4.shared.b16 {%0,%1,%2,%3}, [%4];"
                 : "=r"(r[0]), "=r"(r[1]), "=r"(r[2]), "=r"(r[3]) : "r"(addr));
}

__device__ __forceinline__ void mma_bf16(float* d, const uint32_t* a, const uint32_t* b) {
    asm volatile(
        "mma.sync.aligned.m16n8k16.row.col.f32.bf16.bf16.f32 "
        "{%0,%1,%2,%3}, {%4,%5,%6,%7}, {%8,%9}, {%0,%1,%2,%3};"
        : "+f"(d[0]), "+f"(d[1]), "+f"(d[2]), "+f"(d[3])
        : "r"(a[0]), "r"(a[1]), "r"(a[2]), "r"(a[3]), "r"(b[0]), "r"(b[1]));
}

__device__ __forceinline__ void split_store(float4 v, char* hip, char* lop) {
    __nv_bfloat16 hx = __float2bfloat16(v.x);
    __nv_bfloat16 hy = __float2bfloat16(v.y);
    __nv_bfloat16 hz = __float2bfloat16(v.z);
    __nv_bfloat16 hw = __float2bfloat16(v.w);
    __nv_bfloat16 lx = __float2bfloat16(v.x - __bfloat162float(hx));
    __nv_bfloat16 ly = __float2bfloat16(v.y - __bfloat162float(hy));
    __nv_bfloat16 lz = __float2bfloat16(v.z - __bfloat162float(hz));
    __nv_bfloat16 lw = __float2bfloat16(v.w - __bfloat162float(hw));
    __nv_bfloat162 h01 = __halves2bfloat162(hx, hy);
    __nv_bfloat162 h23 = __halves2bfloat162(hz, hw);
    __nv_bfloat162 l01 = __halves2bfloat162(lx, ly);
    __nv_bfloat162 l23 = __halves2bfloat162(lz, lw);
    *(uint2*)hip = make_uint2(*(unsigned*)&h01, *(unsigned*)&h23);
    *(uint2*)lop = make_uint2(*(unsigned*)&l01, *(unsigned*)&l23);
}

// hi-only bf16 store of fp32x4
__device__ __forceinline__ void hi_store(float4 v, char* hip) {
    __nv_bfloat162 h01 = __halves2bfloat162(__float2bfloat16(v.x), __float2bfloat16(v.y));
    __nv_bfloat162 h23 = __halves2bfloat162(__float2bfloat16(v.z), __float2bfloat16(v.w));
    *(uint2*)hip = make_uint2(*(unsigned*)&h01, *(unsigned*)&h23);
}

__device__ __forceinline__ void split1(float x, __nv_bfloat16& hi, __nv_bfloat16& lo) {
    hi = __float2bfloat16(x);
    lo = __float2bfloat16(x - __bfloat162float(hi));
}

// ---------------- compaction prep ----------------
__global__ void k_prefix(const int* __restrict__ lens) {
    if (threadIdx.x == 0) {
        int a = 0;
        for (int j = 0; j < NCn; j++) { g_off[j] = a; a += lens[j]; }
        g_off[NCn] = a;
    }
}
__global__ void k_zeroC() {
    ((float4*)g_capC)[(size_t)blockIdx.x * 256 + threadIdx.x] = make_float4(0.f, 0.f, 0.f, 0.f);
}
__global__ void k_fillC(const float* __restrict__ cap, const int* __restrict__ lens) {
    int j = blockIdx.x, q = blockIdx.y;
    if (q >= lens[j]) return;
    int dst = g_off[j] + q;
    ((float4*)&g_capC[(size_t)dst * Kn])[threadIdx.x] =
        ((const float4*)&cap[(size_t)(j * Ln + q) * Kn])[threadIdx.x];
}

// ================= logits GEMM: imgH fused, 3-term split-bf16, compacted columns ====
#define ROWP    40
#define MAT_B   (128 * ROWP * 2)
#define STG_B   (4 * MAT_B)
#define GEMM_DSMEM (2 * STG_B)
#define NCHUNK  (Kn / 32)

__global__ void __launch_bounds__(256, 1)
logits_gemm(const float* __restrict__ A, const float* __restrict__ B, float* __restrict__ C,
            const float* __restrict__ hmat) {
    if (blockIdx.x * 128 >= g_off[NCn]) return;
    extern __shared__ char smem[];
    const uint32_t sbase = smem_u32(smem);
    const int tid  = threadIdx.x;
    const int lane = tid & 31;
    const int wid  = tid >> 5;
    const int wm   = wid >> 2;
    const int wc   = wid & 3;

    const int m0 = blockIdx.y * 128;
    const int n0 = blockIdx.x * 128;

    const float* ap[4]; const float* hp[4]; const float* bp[4];
    uint32_t soff[4];
    #pragma unroll
    for (int i = 0; i < 4; i++) {
        int idx = tid + i * 256;
        int r   = idx >> 3;
        int c4  = idx & 7;
        soff[i] = (uint32_t)(r * ROWP + c4 * 4);
        int m = m0 + r;
        int v = m % Vn;
        int h = (m / Vn) % Hn;
        int b = m / (Vn * Hn);
        ap[i] = A    + (size_t)(b * Vn + v) * Kn + c4 * 4;
        hp[i] = hmat + (size_t)h * Kn            + c4 * 4;
        bp[i] = B + (size_t)(n0 + r) * Kn + c4 * 4;
    }

    float acc[4][4][4];
    #pragma unroll
    for (int f = 0; f < 4; f++)
        #pragma unroll
        for (int g = 0; g < 4; g++)
            #pragma unroll
            for (int e = 0; e < 4; e++) acc[f][g][e] = 0.f;

    const int l15 = lane & 15;
    const int lhi = lane >> 4;
    const uint32_t afr = (uint32_t)((wm * 64 + l15) * 80 + lhi * 16);
    const uint32_t bfr = (uint32_t)((wc * 32 + l15) * 80 + lhi * 16);

    {
        char* st = smem;
        #pragma unroll
        for (int i = 0; i < 4; i++) {
            float4 va = *(const float4*)ap[i];
            float4 h4 = *(const float4*)hp[i];
            va.x *= h4.x; va.y *= h4.y; va.z *= h4.z; va.w *= h4.w;
            split_store(va, st + soff[i]*2, st + MAT_B + soff[i]*2);
            float4 vb = *(const float4*)bp[i];
            split_store(vb, st + 2*MAT_B + soff[i]*2, st + 3*MAT_B + soff[i]*2);
        }
    }

    for (int c = 0; c < NCHUNK; c++) {
        __syncthreads();

        float4 va[4], vb[4], h4[4];
        const bool more = (c + 1 < NCHUNK);
        if (more) {
            int k0 = (c + 1) * 32;
            #pragma unroll
            for (int i = 0; i < 4; i++) {
                va[i] = *(const float4*)(ap[i] + k0);
                h4[i] = *(const float4*)(hp[i] + k0);
                vb[i] = *(const float4*)(bp[i] + k0);
            }
        }

        const uint32_t bufb = sbase + (uint32_t)((c & 1) * STG_B);
        #pragma unroll
        for (int kk = 0; kk < 2; kk++) {
            const uint32_t ko = (uint32_t)(kk * 32);
            uint32_t ah[4][4], al[4][4];
            #pragma unroll
            for (int f = 0; f < 4; f++) {
                uint32_t ao = afr + (uint32_t)(f * 16 * 80) + ko;
                ldsm4(ah[f], bufb + ao);
                ldsm4(al[f], bufb + MAT_B + ao);
            }
            uint32_t bh[4][2], bl[4][2];
            #pragma unroll
            for (int p = 0; p < 2; p++) {
                uint32_t bo = bfr + (uint32_t)(p * 16 * 80) + ko;
                uint32_t t[4];
                ldsm4(t, bufb + 2*MAT_B + bo);
                bh[p*2+0][0] = t[0]; bh[p*2+0][1] = t[2];
                bh[p*2+1][0] = t[1]; bh[p*2+1][1] = t[3];
                ldsm4(t, bufb + 3*MAT_B + bo);
                bl[p*2+0][0] = t[0]; bl[p*2+0][1] = t[2];
                bl[p*2+1][0] = t[1]; bl[p*2+1][1] = t[3];
            }
            #pragma unroll
            for (int f = 0; f < 4; f++)
                #pragma unroll
                for (int g = 0; g < 4; g++) {
                    mma_bf16(acc[f][g], ah[f], bh[g]);
                    mma_bf16(acc[f][g], ah[f], bl[g]);
                    mma_bf16(acc[f][g], al[f], bh[g]);
                }
        }

        if (more) {
            char* st = smem + ((c + 1) & 1) * STG_B;
            #pragma unroll
            for (int i = 0; i < 4; i++) {
                float4 v = va[i];
                v.x *= h4[i].x; v.y *= h4[i].y; v.z *= h4[i].z; v.w *= h4[i].w;
                split_store(v, st + soff[i]*2, st + MAT_B + soff[i]*2);
                split_store(vb[i], st + 2*MAT_B + soff[i]*2, st + 3*MAT_B + soff[i]*2);
            }
        }
    }

    const int rbase = m0 + wm * 64 + (lane >> 2);
    const int cbase = n0 + wc * 32 + (lane & 3) * 2;
    #pragma unroll
    for (int f = 0; f < 4; f++) {
        int r = rbase + f * 16;
        #pragma unroll
        for (int g = 0; g < 4; g++) {
            int cc = cbase + g * 8;
            *(float2*)&C[(size_t)r * NCOL + cc]       = make_float2(acc[f][g][0], acc[f][g][1]);
            *(float2*)&C[(size_t)(r + 8) * NCOL + cc] = make_float2(acc[f][g][2], acc[f][g][3]);
        }
    }
}

// ================= gated-phase GEMM (1-term, pure bf16) =================
#define PMAT_B  (128 * ROWP * 2)
#define PSTG_B  (2 * PMAT_B)          // Ah, Bh
#define PGEMM_DSMEM (2 * PSTG_B)      // 40960

__global__ void __launch_bounds__(256, 1)
gated_gemm(const __nv_bfloat16* __restrict__ Gh, const __nv_bfloat16* __restrict__ L2h,
           const __nv_bfloat16* __restrict__ Wh,
           float* __restrict__ Cq, float* __restrict__ Ck, float* __restrict__ Cw) {
    extern __shared__ char smem[];
    const uint32_t sbase = smem_u32(smem);
    const int tid  = threadIdx.x;
    const int lane = tid & 31;
    const int wid  = tid >> 5;
    const int wm   = wid >> 2;
    const int wc   = wid & 3;

    const int nx = blockIdx.x;
    const int m0 = blockIdx.y * 128;

    const __nv_bfloat16* Ah = (nx < 16) ? Gh : L2h;
    const __nv_bfloat16* Bp = Wh + (size_t)(nx * 128) * Kn;
    float* C; int n0c;
    if (nx < 8)       { C = Cq; n0c = nx * 128; }
    else if (nx < 16) { C = Ck; n0c = (nx - 8) * 128; }
    else              { C = Cw; n0c = (nx - 16) * 128; }

    const __nv_bfloat16* ahp[2]; const __nv_bfloat16* bhp[2];
    uint32_t so[2];
    #pragma unroll
    for (int i = 0; i < 2; i++) {
        int idx = tid + i * 256;
        int r = idx >> 2, c8 = idx & 3;
        so[i] = (uint32_t)(r * ROWP + c8 * 8) * 2;
        ahp[i] = Ah + (size_t)(m0 + r) * Kn + c8 * 8;
        bhp[i] = Bp + (size_t)r * Kn + c8 * 8;
    }

    float acc[4][4][4];
    #pragma unroll
    for (int f = 0; f < 4; f++)
        #pragma unroll
        for (int g = 0; g < 4; g++)
            #pragma unroll
            for (int e = 0; e < 4; e++) acc[f][g][e] = 0.f;

    const int l15 = lane & 15;
    const int lhi = lane >> 4;
    const uint32_t afr = (uint32_t)((wm * 64 + l15) * 80 + lhi * 16);
    const uint32_t bfr = (uint32_t)((wc * 32 + l15) * 80 + lhi * 16);

    {
        char* st = smem;
        #pragma unroll
        for (int i = 0; i < 2; i++) {
            *(uint4*)(st + so[i])          = *(const uint4*)ahp[i];
            *(uint4*)(st + PMAT_B + so[i]) = *(const uint4*)bhp[i];
        }
    }

    for (int c = 0; c < NCHUNK; c++) {
        __syncthreads();

        uint4 va[2], vb[2];
        const bool more = (c + 1 < NCHUNK);
        if (more) {
            int k0 = (c + 1) * 32;
            #pragma unroll
            for (int i = 0; i < 2; i++) {
                va[i] = *(const uint4*)(ahp[i] + k0);
                vb[i] = *(const uint4*)(bhp[i] + k0);
            }
        }

        const uint32_t bufb = sbase + (uint32_t)((c & 1) * PSTG_B);
        #pragma unroll
        for (int kk = 0; kk < 2; kk++) {
            const uint32_t ko = (uint32_t)(kk * 32);
            uint32_t ah[4][4];
            #pragma unroll
            for (int f = 0; f < 4; f++) {
                uint32_t ao = afr + (uint32_t)(f * 16 * 80) + ko;
                ldsm4(ah[f], bufb + ao);
            }
            uint32_t bh[4][2];
            #pragma unroll
            for (int p = 0; p < 2; p++) {
                uint32_t bo = bfr + (uint32_t)(p * 16 * 80) + ko;
                uint32_t t[4];
                ldsm4(t, bufb + PMAT_B + bo);
                bh[p*2+0][0] = t[0]; bh[p*2+0][1] = t[2];
                bh[p*2+1][0] = t[1]; bh[p*2+1][1] = t[3];
            }
            #pragma unroll
            for (int f = 0; f < 4; f++)
                #pragma unroll
                for (int g = 0; g < 4; g++)
                    mma_bf16(acc[f][g], ah[f], bh[g]);
        }

        if (more) {
            char* st = smem + ((c + 1) & 1) * PSTG_B;
            #pragma unroll
            for (int i = 0; i < 2; i++) {
                *(uint4*)(st + so[i])          = va[i];
                *(uint4*)(st + PMAT_B + so[i]) = vb[i];
            }
        }
    }

    const int rbase = m0 + wm * 64 + (lane >> 2);
    const int cbase = n0c + wc * 32 + (lane & 3) * 2;
    #pragma unroll
    for (int f = 0; f < 4; f++) {
        int r = rbase + f * 16;
        #pragma unroll
        for (int g = 0; g < 4; g++) {
            int cc = cbase + g * 8;
            *(float2*)&C[(size_t)r * Kn + cc]       = make_float2(acc[f][g][0], acc[f][g][1]);
            *(float2*)&C[(size_t)(r + 8) * Kn + cc] = make_float2(acc[f][g][2], acc[f][g][3]);
        }
    }
}

// ---------------- weight pre-split ----------------
__global__ void k_split_w(const float* __restrict__ W1, const float* __restrict__ W2,
                          const float* __restrict__ W3) {
    int idx = blockIdx.x * 256 + threadIdx.x;
    int r  = idx >> 8;
    int c4 = (idx & 255) * 4;
    const float* src = (r < 1024) ? W1 + (size_t)r * Kn
                     : (r < 2048) ? W2 + (size_t)(r - 1024) * Kn
                                  : W3 + (size_t)(r - 2048) * Kn;
    float4 v = *(const float4*)&src[c4];
    hi_store(v, (char*)&g_Wh[(size_t)r * Kn + c4]);
}

// ================= l_all: fused softmax + warp-specialized tensor cores ============
#define LPROW      56
#define L_OFF_PH   0
#define L_OFF_PL   37632
#define L_OFF_CH   75264
#define L_OFF_CL   89600
#define L_OFF_IMG  103936
#define L_OFF_M1   122368
#define L_OFF_MX   219136
#define LALL_SMEM  219264

__global__ void __launch_bounds__(512, 1)
k_lall_tc(const float* __restrict__ img, const float* __restrict__ cap,
          const int* __restrict__ lens) {
    extern __shared__ char sm[];
    const uint32_t sb = smem_u32(sm);
    __nv_bfloat16* pH = (__nv_bfloat16*)(sm + L_OFF_PH);
    __nv_bfloat16* pL = (__nv_bfloat16*)(sm + L_OFF_PL);
    float*        M1s = (float*)(sm + L_OFF_M1);
    float*       pRaw = (float*)(sm + L_OFF_M1);
    float*       invs = (float*)(sm + L_OFF_MX);

    const int bid = blockIdx.x;           // j*Bn + b
    const int b = bid % Bn;
    const int j = bid / Bn;
    const int tid  = threadIdx.x;
    const int lane = tid & 31;
    const int wid  = tid >> 5;
    const int l15  = lane & 15;
    const int lhi  = lane >> 4;
    const int len  = lens[j];
    const int off  = g_off[j];
    const int nks  = (len + 15) >> 4;
    const float NEG = -3.402823466e38f;

    for (int e = tid; e < 324 * 48; e += 512) {
        int m = e / 48, q = e - m * 48;
        int h = m / 36, v = m - h * 36;
        float x = NEG;
        if (q < len)
            x = g_logits[(size_t)((b * Hn + h) * Vn + v) * NCOL + off + q];
        pRaw[e] = x;
    }
    __syncthreads();

    if (wid < Hn) {
        const int h = wid;
        float mx = NEG;
        for (int e = lane; e < 1728; e += 32) mx = fmaxf(mx, pRaw[h * 1728 + e]);
        #pragma unroll
        for (int o = 16; o > 0; o >>= 1) mx = fmaxf(mx, __shfl_xor_sync(0xffffffffu, mx, o));
        float s = 0.f;
        for (int e = lane; e < 1728; e += 32) {
            float x = expf(pRaw[h * 1728 + e] - mx);
            pRaw[h * 1728 + e] = x;
            s += x;
        }
        #pragma unroll
        for (int o = 16; o > 0; o >>= 1) s += __shfl_xor_sync(0xffffffffu, s, o);
        if (lane == 0) invs[h] = 1.f / s;
    }
    __syncthreads();

    for (int e = tid; e < 336 * 48; e += 512) {
        int m = e / 48, q = e - m * 48;
        float x = 0.f;
        if (m < 324) x = pRaw[m * 48 + q] * invs[m / 36];
        __nv_bfloat16 hi, lo; split1(x, hi, lo);
        pH[m * LPROW + q] = hi;
        pL[m * LPROW + q] = lo;
    }
    {
        const int kt = tid & 63, g8 = tid >> 6;
        __nv_bfloat16* cH0 = (__nv_bfloat16*)(sm + L_OFF_CH);
        __nv_bfloat16* cL0 = (__nv_bfloat16*)(sm + L_OFF_CL);
        float*         im0 = (float*)(sm + L_OFF_IMG);
        for (int q = g8; q < 48; q += 8) {
            float x = cap[(size_t)(j * Ln + q) * Kn + kt];
            __nv_bfloat16 hi, lo; split1(x, hi, lo);
            cH0[kt * LPROW + q] = hi;
            cL0[kt * LPROW + q] = lo;
        }
        for (int v = g8; v < 36; v += 8)
            im0[v * 64 + kt] = img[(size_t)(b * Vn + v) * Kn + kt];
    }
    __syncthreads();

    for (int t = 0; t < Kn / 64; t++) {
        const int k0 = t * 64;
        const uint32_t cbuf = (uint32_t)((t & 1) * 7168);
        const uint32_t ibuf = (uint32_t)((t & 1) * 9216);

        if (wid < 14) {
            const int wn = wid & 1;
            const int wg = wid >> 1;
            float acc[3][4][4];
            #pragma unroll
            for (int i = 0; i < 3; i++)
                #pragma unroll
                for (int nt = 0; nt < 4; nt++)
                    #pragma unroll
                    for (int e = 0; e < 4; e++) acc[i][nt][e] = 0.f;

            #pragma unroll 3
            for (int ks = 0; ks < nks; ks++) {
                uint32_t bh[4][2], bl[4][2];
                #pragma unroll
                for (int p2 = 0; p2 < 2; p2++) {
                    uint32_t bo = (uint32_t)((wn * 32 + p2 * 16 + l15) * 112 + lhi * 16 + ks * 32);
                    uint32_t tt[4];
                    ldsm4(tt, sb + L_OFF_CH + cbuf + bo);
                    bh[p2*2+0][0] = tt[0]; bh[p2*2+0][1] = tt[2];
                    bh[p2*2+1][0] = tt[1]; bh[p2*2+1][1] = tt[3];
                    ldsm4(tt, sb + L_OFF_CL + cbuf + bo);
                    bl[p2*2+0][0] = tt[0]; bl[p2*2+0][1] = tt[2];
                    bl[p2*2+1][0] = tt[1]; bl[p2*2+1][1] = tt[3];
                }
                #pragma unroll
                for (int i = 0; i < 3; i++) {
                    uint32_t ao = (uint32_t)((wg * 48 + i * 16 + l15) * 112 + lhi * 16 + ks * 32);
                    uint32_t ah[4], al[4];
                    ldsm4(ah, sb + L_OFF_PH + ao);
                    ldsm4(al, sb + L_OFF_PL + ao);
                    #pragma unroll
                    for (int nt = 0; nt < 4; nt++) {
                        mma_bf16(acc[i][nt], ah, bh[nt]);
                        mma_bf16(acc[i][nt], ah, bl[nt]);
                        mma_bf16(acc[i][nt], al, bh[nt]);
                    }
                }
            }
            #pragma unroll
            for (int i = 0; i < 3; i++) {
                int r = (wg * 3 + i) * 16 + (lane >> 2);
                #pragma unroll
                for (int nt = 0; nt < 4; nt++) {
                    int c = wn * 32 + nt * 8 + (lane & 3) * 2;
                    *(float2*)&M1s[r * 72 + c]       = make_float2(acc[i][nt][0], acc[i][nt][1]);
                    *(float2*)&M1s[(r + 8) * 72 + c] = make_float2(acc[i][nt][2], acc[i][nt][3]);
                }
            }
        } else if (t + 1 < Kn / 64) {
            const int lt = tid - 448;
            const int kn0 = (t + 1) * 64;
            __nv_bfloat16* cHB = (__nv_bfloat16*)(sm + L_OFF_CH + ((t + 1) & 1) * 7168);
            __nv_bfloat16* cLB = (__nv_bfloat16*)(sm + L_OFF_CL + ((t + 1) & 1) * 7168);
            float*         imB = (float*)(sm + L_OFF_IMG + ((t + 1) & 1) * 9216);
            for (int q = 0; q < 48; q++) {
                float x = cap[(size_t)(j * Ln + q) * Kn + kn0 + lt];
                __nv_bfloat16 hi, lo; split1(x, hi, lo);
                cHB[lt * LPROW + q] = hi;
                cLB[lt * LPROW + q] = lo;
            }
            for (int v = 0; v < 36; v++)
                imB[v * 64 + lt] = img[(size_t)(b * Vn + v) * Kn + kn0 + lt];
        }
        __syncthreads();

        const float* imC = (const float*)(sm + L_OFF_IMG + ibuf);
        for (int e = tid; e < Hn * 64; e += 512) {
            int h = e >> 6, kt = e & 63;
            float a = 0.f;
            #pragma unroll
            for (int v = 0; v < Vn; v++)
                a += M1s[(h * Vn + v) * 72 + kt] * imC[v * 64 + kt];
            g_lall[(size_t)(bid * Hn + h) * Kn + k0 + kt] = a;
        }
        __syncthreads();
    }
}

// ---------------- gated elementwise ----------------
__global__ void k_e1(const float* __restrict__ l1, int lda1,
                     const float* __restrict__ l2, int lda2) {
    int idx = blockIdx.x * blockDim.x + threadIdx.x;
    int m  = idx / (Kn / 4);
    int k4 = (idx % (Kn / 4)) * 4;
    float4 a = *(const float4*)&l1[(size_t)m * lda1 + k4];
    float4 c = *(const float4*)&l2[(size_t)m * lda2 + k4];
    float4 g = make_float4(a.x + tanhf(c.x), a.y + tanhf(c.y),
                           a.z + tanhf(c.z), a.w + tanhf(c.w));
    size_t off = (size_t)m * Kn + k4;
    hi_store(g, (char*)(g_Gh + off));
    hi_store(c, (char*)(g_L2h + off));
}

__global__ void __launch_bounds__(256) k_e2f(const float* __restrict__ l1, int lda1,
                                             const float* __restrict__ l2, int lda2,
                                             const float* __restrict__ b1,
                                             const float* __restrict__ b2,
                                             const float* __restrict__ b3,
                                             const float* __restrict__ l1n, int last) {
    const int m  = blockIdx.x;
    const int k4 = threadIdx.x * 4;
    float4 a1 = *(const float4*)&l1[(size_t)m * lda1 + k4];
    float4 a2 = *(const float4*)&l2[(size_t)m * lda2 + k4];
    float4 qv = *(const float4*)&g_Qg [(size_t)m * Kn + k4];
    float4 kv = *(const float4*)&g_Kg [(size_t)m * Kn + k4];
    float4 wv = *(const float4*)&g_W3o[(size_t)m * Kn + k4];
    float4 vb1 = *(const float4*)&b1[k4];
    float4 vb2 = *(const float4*)&b2[k4];
    float4 vb3 = *(const float4*)&b3[k4];

    float4 x;
    x.x = tanhf(a1.x) * sigmoidf_(qv.x + vb1.x) + a1.x + (wv.x + vb3.x) * sigmoidf_(kv.x + vb2.x) + a2.x;
    x.y = tanhf(a1.y) * sigmoidf_(qv.y + vb1.y) + a1.y + (wv.y + vb3.y) * sigmoidf_(kv.y + vb2.y) + a2.y;
    x.z = tanhf(a1.z) * sigmoidf_(qv.z + vb1.z) + a1.z + (wv.z + vb3.z) * sigmoidf_(kv.z + vb2.z) + a2.z;
    x.w = tanhf(a1.w) * sigmoidf_(qv.w + vb1.w) + a1.w + (wv.w + vb3.w) * sigmoidf_(kv.w + vb2.w) + a2.w;

    float ss = x.x * x.x + x.y * x.y + x.z * x.z + x.w * x.w;
    float tot = blockReduceSum256(ss);
    float inv = 1.f / (sqrtf(tot) + 1e-8f);
    float4 o = make_float4(x.x * inv, x.y * inv, x.z * inv, x.w * inv);
    size_t off = (size_t)m * Kn + k4;
    *(float4*)&g_carry[off] = o;

    if (!last) {
        hi_store(o, (char*)(g_L2h + off));
        float4 a = *(const float4*)&l1n[(size_t)m * (Hn * Kn) + k4];
        float4 g = make_float4(a.x + tanhf(o.x), a.y + tanhf(o.y),
                               a.z + tanhf(o.z), a.w + tanhf(o.w));
        hi_store(g, (char*)(g_Gh + off));
    }
}

// ---------------- final ----------------
__global__ void k_final(float* __restrict__ out) {
    const int m = blockIdx.x;
    const int b = m % Bn;
    const int j = m / Bn;
    float s = 0.f;
    for (int k = threadIdx.x; k < Kn; k += 256) s += g_carry[(size_t)m * Kn + k];
    float tot = blockReduceSum256(s);
    if (threadIdx.x == 0) out[b * NCn + j] = tot;
}

// ---------------- launcher ----------------
extern "C" void kernel_launch(void* const* d_in, const int* in_sizes, int n_in,
                              void* d_out, int out_size) {
    const float* img  = (const float*)d_in[0];
    const float* cap  = (const float*)d_in[1];
    const int*   lens = (const int*)  d_in[2];
    const float* hmat = (const float*)d_in[3];
    /* d_in[4] = h_bias: softmax-invariant, unused */
    const float* W1 = (const float*)d_in[5];
    const float* b1 = (const float*)d_in[6];
    const float* W2 = (const float*)d_in[7];
    const float* b2 = (const float*)d_in[8];
    const float* W3 = (const float*)d_in[9];
    const float* b3 = (const float*)d_in[10];
    float* out = (float*)d_out;

    cudaFuncSetAttribute(k_lall_tc, cudaFuncAttributeMaxDynamicSharedMemorySize, LALL_SMEM);
    cudaFuncSetAttribute(logits_gemm, cudaFuncAttributeMaxDynamicSharedMemorySize, GEMM_DSMEM);
    cudaFuncSetAttribute(gated_gemm, cudaFuncAttributeMaxDynamicSharedMemorySize, PGEMM_DSMEM);

    float *pLall, *pQ, *pKg, *pW3o, *pCar, *pLog, *pCapC;
    __nv_bfloat16 *pWh, *pGh, *pL2h;
    cudaGetSymbolAddress((void**)&pLog,  g_logits);
    cudaGetSymbolAddress((void**)&pCapC, g_capC);
    cudaGetSymbolAddress((void**)&pLall, g_lall);
    cudaGetSymbolAddress((void**)&pQ,    g_Qg);
    cudaGetSymbolAddress((void**)&pKg,   g_Kg);
    cudaGetSymbolAddress((void**)&pW3o,  g_W3o);
    cudaGetSymbolAddress((void**)&pCar,  g_carry);
    cudaGetSymbolAddress((void**)&pWh,   g_Wh);
    cudaGetSymbolAddress((void**)&pGh,   g_Gh);
    cudaGetSymbolAddress((void**)&pL2h,  g_L2h);

    k_split_w<<<3072, 256>>>(W1, W2, W3);

    // Phase 0: compaction prep
    k_prefix<<<1, 32>>>(lens);
    k_zeroC<<<NCOL, 256>>>();
    k_fillC<<<dim3(NCn, Ln), 256>>>(cap, lens);

    // Phase 1: logits GEMM over compacted active columns
    logits_gemm<<<dim3(NCOL / 128, MR / 128), 256, GEMM_DSMEM>>>(img, pCapC, pLog, hmat);

    // Phase 2: attended features l_all (fused softmax + tensor cores)
    k_lall_tc<<<NCn * Bn, 512, LALL_SMEM>>>(img, cap, lens);

    // Phase 3: 8 gated steps (1-term bf16 GEMM)
    k_e1<<<GMr * (Kn / 4) / 256, 256>>>(pLall, Hn * Kn, pLall + Kn, Hn * Kn);
    for (int s = 0; s < 8; s++) {
        int hs = (s == 0) ? 0 : (s + 1);
        const float* l1 = pLall + (size_t)hs * Kn;  int lda1 = Hn * Kn;
        const float* l2; int lda2;
        if (s == 0) { l2 = pLall + Kn; lda2 = Hn * Kn; }
        else        { l2 = pCar;       lda2 = Kn; }
        const float* l1n = (s < 7) ? (pLall + (size_t)(s + 2) * Kn) : pLall;

        gated_gemm<<<dim3(24, GMr / 128), 256, PGEMM_DSMEM>>>(
            pGh, pL2h, pWh, pQ, pKg, pW3o);
        k_e2f<<<GMr, 256>>>(l1, lda1, l2, lda2, b1, b2, b3, l1n, s == 7);
    }

    // Phase 4: feature-sum -> (B, Nc)
    k_final<<<GMr, 256>>>(out);
}

// round 17
// speedup vs baseline: 1.6247x; 1.0729x over previous
#include <cuda_runtime.h>
#include <cuda_bf16.h>
#include <math.h>
#include <stdint.h>

// Problem constants
#define Bn   64
#define Vn   36
#define Kn   1024
#define NCn  64
#define Ln   48
#define Hn   9

#define MR    (Bn*Hn*Vn)      // 20736
#define NCOL  (NCn*Ln)        // 3072
#define GMr   (NCn*Bn)        // 4096

// ---------------- scratch ----------------
__device__ float g_logits[(size_t)MR  * NCOL];    // compacted-column logits
__device__ float g_capC  [(size_t)NCOL * Kn];     // column-compacted cap
__device__ int   g_off   [NCn + 1];
__device__ float g_lall  [(size_t)GMr * Hn * Kn];
__device__ float g_Qg    [(size_t)GMr * Kn];
__device__ float g_Kg    [(size_t)GMr * Kn];
__device__ float g_W3o   [(size_t)GMr * Kn];
__device__ float g_carry [(size_t)GMr * Kn];
__device__ __nv_bfloat16 g_Wh [(size_t)3072 * Kn];
__device__ __nv_bfloat16 g_Gh [(size_t)GMr * Kn];
__device__ __nv_bfloat16 g_L2h[(size_t)GMr * Kn];

// ---------------- small helpers ----------------
__device__ __forceinline__ float sigmoidf_(float x) { return 1.f / (1.f + expf(-x)); }

__device__ __forceinline__ float blockReduceSum256(float v) {
    __shared__ float red[8];
    #pragma unroll
    for (int o = 16; o > 0; o >>= 1) v += __shfl_xor_sync(0xffffffffu, v, o);
    int tid = threadIdx.x;
    if ((tid & 31) == 0) red[tid >> 5] = v;
    __syncthreads();
    float s = 0.f;
    int nw = blockDim.x >> 5;
    #pragma unroll
    for (int i = 0; i < 8; i++) if (i < nw) s += red[i];
    __syncthreads();
    return s;
}

// ---------------- mma.sync primitives ----------------
__device__ __forceinline__ uint32_t smem_u32(const void* p) {
    uint32_t a;
    asm("{ .reg .u64 t; cvta.to.shared.u64 t, %1; cvt.u32.u64 %0, t; }" : "=r"(a) : "l"(p));
    return a;
}

__device__ __forceinline__ void ldsm4(uint32_t* r, uint32_t addr) {
    asm volatile("ldmatrix.sync.aligned.m8n8.x4.shared.b16 {%0,%1,%2,%3}, [%4];"
                 : "=r"(r[0]), "=r"(r[1]), "=r"(r[2]), "=r"(r[3]) : "r"(addr));
}

__device__ __forceinline__ void mma_bf16(float* d, const uint32_t* a, const uint32_t* b) {
    asm volatile(
        "mma.sync.aligned.m16n8k16.row.col.f32.bf16.bf16.f32 "
        "{%0,%1,%2,%3}, {%4,%5,%6,%7}, {%8,%9}, {%0,%1,%2,%3};"
        : "+f"(d[0]), "+f"(d[1]), "+f"(d[2]), "+f"(d[3])
        : "r"(a[0]), "r"(a[1]), "r"(a[2]), "r"(a[3]), "r"(b[0]), "r"(b[1]));
}

__device__ __forceinline__ void split_store(float4 v, char* hip, char* lop) {
    __nv_bfloat16 hx = __float2bfloat16(v.x);
    __nv_bfloat16 hy = __float2bfloat16(v.y);
    __nv_bfloat16 hz = __float2bfloat16(v.z);
    __nv_bfloat16 hw = __float2bfloat16(v.w);
    __nv_bfloat16 lx = __float2bfloat16(v.x - __bfloat162float(hx));
    __nv_bfloat16 ly = __float2bfloat16(v.y - __bfloat162float(hy));
    __nv_bfloat16 lz = __float2bfloat16(v.z - __bfloat162float(hz));
    __nv_bfloat16 lw = __float2bfloat16(v.w - __bfloat162float(hw));
    __nv_bfloat162 h01 = __halves2bfloat162(hx, hy);
    __nv_bfloat162 h23 = __halves2bfloat162(hz, hw);
    __nv_bfloat162 l01 = __halves2bfloat162(lx, ly);
    __nv_bfloat162 l23 = __halves2bfloat162(lz, lw);
    *(uint2*)hip = make_uint2(*(unsigned*)&h01, *(unsigned*)&h23);
    *(uint2*)lop = make_uint2(*(unsigned*)&l01, *(unsigned*)&l23);
}

// hi-only bf16 store of fp32x4
__device__ __forceinline__ void hi_store(float4 v, char* hip) {
    __nv_bfloat162 h01 = __halves2bfloat162(__float2bfloat16(v.x), __float2bfloat16(v.y));
    __nv_bfloat162 h23 = __halves2bfloat162(__float2bfloat16(v.z), __float2bfloat16(v.w));
    *(uint2*)hip = make_uint2(*(unsigned*)&h01, *(unsigned*)&h23);
}

__device__ __forceinline__ void split1(float x, __nv_bfloat16& hi, __nv_bfloat16& lo) {
    hi = __float2bfloat16(x);
    lo = __float2bfloat16(x - __bfloat162float(hi));
}

// ---------------- compaction prep ----------------
__global__ void k_prefix(const int* __restrict__ lens) {
    if (threadIdx.x == 0) {
        int a = 0;
        for (int j = 0; j < NCn; j++) { g_off[j] = a; a += lens[j]; }
        g_off[NCn] = a;
    }
}
__global__ void k_zeroC() {
    ((float4*)g_capC)[(size_t)blockIdx.x * 256 + threadIdx.x] = make_float4(0.f, 0.f, 0.f, 0.f);
}
__global__ void k_fillC(const float* __restrict__ cap, const int* __restrict__ lens) {
    int j = blockIdx.x, q = blockIdx.y;
    if (q >= lens[j]) return;
    int dst = g_off[j] + q;
    ((float4*)&g_capC[(size_t)dst * Kn])[threadIdx.x] =
        ((const float4*)&cap[(size_t)(j * Ln + q) * Kn])[threadIdx.x];
}

// ================= logits GEMM: imgH fused, 3-term split-bf16, compacted columns ====
#define ROWP    40
#define MAT_B   (128 * ROWP * 2)
#define STG_B   (4 * MAT_B)
#define GEMM_DSMEM (2 * STG_B)
#define NCHUNK  (Kn / 32)

__global__ void __launch_bounds__(256, 1)
logits_gemm(const float* __restrict__ A, const float* __restrict__ B, float* __restrict__ C,
            const float* __restrict__ hmat) {
    if (blockIdx.x * 128 >= g_off[NCn]) return;
    extern __shared__ char smem[];
    const uint32_t sbase = smem_u32(smem);
    const int tid  = threadIdx.x;
    const int lane = tid & 31;
    const int wid  = tid >> 5;
    const int wm   = wid >> 2;
    const int wc   = wid & 3;

    const int m0 = blockIdx.y * 128;
    const int n0 = blockIdx.x * 128;

    const float* ap[4]; const float* hp[4]; const float* bp[4];
    uint32_t soff[4];
    #pragma unroll
    for (int i = 0; i < 4; i++) {
        int idx = tid + i * 256;
        int r   = idx >> 3;
        int c4  = idx & 7;
        soff[i] = (uint32_t)(r * ROWP + c4 * 4);
        int m = m0 + r;
        int v = m % Vn;
        int h = (m / Vn) % Hn;
        int b = m / (Vn * Hn);
        ap[i] = A    + (size_t)(b * Vn + v) * Kn + c4 * 4;
        hp[i] = hmat + (size_t)h * Kn            + c4 * 4;
        bp[i] = B + (size_t)(n0 + r) * Kn + c4 * 4;
    }

    float acc[4][4][4];
    #pragma unroll
    for (int f = 0; f < 4; f++)
        #pragma unroll
        for (int g = 0; g < 4; g++)
            #pragma unroll
            for (int e = 0; e < 4; e++) acc[f][g][e] = 0.f;

    const int l15 = lane & 15;
    const int lhi = lane >> 4;
    const uint32_t afr = (uint32_t)((wm * 64 + l15) * 80 + lhi * 16);
    const uint32_t bfr = (uint32_t)((wc * 32 + l15) * 80 + lhi * 16);

    {
        char* st = smem;
        #pragma unroll
        for (int i = 0; i < 4; i++) {
            float4 va = *(const float4*)ap[i];
            float4 h4 = *(const float4*)hp[i];
            va.x *= h4.x; va.y *= h4.y; va.z *= h4.z; va.w *= h4.w;
            split_store(va, st + soff[i]*2, st + MAT_B + soff[i]*2);
            float4 vb = *(const float4*)bp[i];
            split_store(vb, st + 2*MAT_B + soff[i]*2, st + 3*MAT_B + soff[i]*2);
        }
    }

    for (int c = 0; c < NCHUNK; c++) {
        __syncthreads();

        float4 va[4], vb[4], h4[4];
        const bool more = (c + 1 < NCHUNK);
        if (more) {
            int k0 = (c + 1) * 32;
            #pragma unroll
            for (int i = 0; i < 4; i++) {
                va[i] = *(const float4*)(ap[i] + k0);
                h4[i] = *(const float4*)(hp[i] + k0);
                vb[i] = *(const float4*)(bp[i] + k0);
            }
        }

        const uint32_t bufb = sbase + (uint32_t)((c & 1) * STG_B);
        #pragma unroll
        for (int kk = 0; kk < 2; kk++) {
            const uint32_t ko = (uint32_t)(kk * 32);
            uint32_t ah[4][4], al[4][4];
            #pragma unroll
            for (int f = 0; f < 4; f++) {
                uint32_t ao = afr + (uint32_t)(f * 16 * 80) + ko;
                ldsm4(ah[f], bufb + ao);
                ldsm4(al[f], bufb + MAT_B + ao);
            }
            uint32_t bh[4][2], bl[4][2];
            #pragma unroll
            for (int p = 0; p < 2; p++) {
                uint32_t bo = bfr + (uint32_t)(p * 16 * 80) + ko;
                uint32_t t[4];
                ldsm4(t, bufb + 2*MAT_B + bo);
                bh[p*2+0][0] = t[0]; bh[p*2+0][1] = t[2];
                bh[p*2+1][0] = t[1]; bh[p*2+1][1] = t[3];
                ldsm4(t, bufb + 3*MAT_B + bo);
                bl[p*2+0][0] = t[0]; bl[p*2+0][1] = t[2];
                bl[p*2+1][0] = t[1]; bl[p*2+1][1] = t[3];
            }
            #pragma unroll
            for (int f = 0; f < 4; f++)
                #pragma unroll
                for (int g = 0; g < 4; g++) {
                    mma_bf16(acc[f][g], ah[f], bh[g]);
                    mma_bf16(acc[f][g], ah[f], bl[g]);
                    mma_bf16(acc[f][g], al[f], bh[g]);
                }
        }

        if (more) {
            char* st = smem + ((c + 1) & 1) * STG_B;
            #pragma unroll
            for (int i = 0; i < 4; i++) {
                float4 v = va[i];
                v.x *= h4[i].x; v.y *= h4[i].y; v.z *= h4[i].z; v.w *= h4[i].w;
                split_store(v, st + soff[i]*2, st + MAT_B + soff[i]*2);
                split_store(vb[i], st + 2*MAT_B + soff[i]*2, st + 3*MAT_B + soff[i]*2);
            }
        }
    }

    const int rbase = m0 + wm * 64 + (lane >> 2);
    const int cbase = n0 + wc * 32 + (lane & 3) * 2;
    #pragma unroll
    for (int f = 0; f < 4; f++) {
        int r = rbase + f * 16;
        #pragma unroll
        for (int g = 0; g < 4; g++) {
            int cc = cbase + g * 8;
            *(float2*)&C[(size_t)r * NCOL + cc]       = make_float2(acc[f][g][0], acc[f][g][1]);
            *(float2*)&C[(size_t)(r + 8) * NCOL + cc] = make_float2(acc[f][g][2], acc[f][g][3]);
        }
    }
}

// ================= gated-phase GEMM (1-term, pure bf16) =================
#define PMAT_B  (128 * ROWP * 2)
#define PSTG_B  (2 * PMAT_B)
#define PGEMM_DSMEM (2 * PSTG_B)

__global__ void __launch_bounds__(256, 1)
gated_gemm(const __nv_bfloat16* __restrict__ Gh, const __nv_bfloat16* __restrict__ L2h,
           const __nv_bfloat16* __restrict__ Wh,
           float* __restrict__ Cq, float* __restrict__ Ck, float* __restrict__ Cw) {
    extern __shared__ char smem[];
    const uint32_t sbase = smem_u32(smem);
    const int tid  = threadIdx.x;
    const int lane = tid & 31;
    const int wid  = tid >> 5;
    const int wm   = wid >> 2;
    const int wc   = wid & 3;

    const int nx = blockIdx.x;
    const int m0 = blockIdx.y * 128;

    const __nv_bfloat16* Ah = (nx < 16) ? Gh : L2h;
    const __nv_bfloat16* Bp = Wh + (size_t)(nx * 128) * Kn;
    float* C; int n0c;
    if (nx < 8)       { C = Cq; n0c = nx * 128; }
    else if (nx < 16) { C = Ck; n0c = (nx - 8) * 128; }
    else              { C = Cw; n0c = (nx - 16) * 128; }

    const __nv_bfloat16* ahp[2]; const __nv_bfloat16* bhp[2];
    uint32_t so[2];
    #pragma unroll
    for (int i = 0; i < 2; i++) {
        int idx = tid + i * 256;
        int r = idx >> 2, c8 = idx & 3;
        so[i] = (uint32_t)(r * ROWP + c8 * 8) * 2;
        ahp[i] = Ah + (size_t)(m0 + r) * Kn + c8 * 8;
        bhp[i] = Bp + (size_t)r * Kn + c8 * 8;
    }

    float acc[4][4][4];
    #pragma unroll
    for (int f = 0; f < 4; f++)
        #pragma unroll
        for (int g = 0; g < 4; g++)
            #pragma unroll
            for (int e = 0; e < 4; e++) acc[f][g][e] = 0.f;

    const int l15 = lane & 15;
    const int lhi = lane >> 4;
    const uint32_t afr = (uint32_t)((wm * 64 + l15) * 80 + lhi * 16);
    const uint32_t bfr = (uint32_t)((wc * 32 + l15) * 80 + lhi * 16);

    {
        char* st = smem;
        #pragma unroll
        for (int i = 0; i < 2; i++) {
            *(uint4*)(st + so[i])          = *(const uint4*)ahp[i];
            *(uint4*)(st + PMAT_B + so[i]) = *(const uint4*)bhp[i];
        }
    }

    for (int c = 0; c < NCHUNK; c++) {
        __syncthreads();

        uint4 va[2], vb[2];
        const bool more = (c + 1 < NCHUNK);
        if (more) {
            int k0 = (c + 1) * 32;
            #pragma unroll
            for (int i = 0; i < 2; i++) {
                va[i] = *(const uint4*)(ahp[i] + k0);
                vb[i] = *(const uint4*)(bhp[i] + k0);
            }
        }

        const uint32_t bufb = sbase + (uint32_t)((c & 1) * PSTG_B);
        #pragma unroll
        for (int kk = 0; kk < 2; kk++) {
            const uint32_t ko = (uint32_t)(kk * 32);
            uint32_t ah[4][4];
            #pragma unroll
            for (int f = 0; f < 4; f++) {
                uint32_t ao = afr + (uint32_t)(f * 16 * 80) + ko;
                ldsm4(ah[f], bufb + ao);
            }
            uint32_t bh[4][2];
            #pragma unroll
            for (int p = 0; p < 2; p++) {
                uint32_t bo = bfr + (uint32_t)(p * 16 * 80) + ko;
                uint32_t t[4];
                ldsm4(t, bufb + PMAT_B + bo);
                bh[p*2+0][0] = t[0]; bh[p*2+0][1] = t[2];
                bh[p*2+1][0] = t[1]; bh[p*2+1][1] = t[3];
            }
            #pragma unroll
            for (int f = 0; f < 4; f++)
                #pragma unroll
                for (int g = 0; g < 4; g++)
                    mma_bf16(acc[f][g], ah[f], bh[g]);
        }

        if (more) {
            char* st = smem + ((c + 1) & 1) * PSTG_B;
            #pragma unroll
            for (int i = 0; i < 2; i++) {
                *(uint4*)(st + so[i])          = va[i];
                *(uint4*)(st + PMAT_B + so[i]) = vb[i];
            }
        }
    }

    const int rbase = m0 + wm * 64 + (lane >> 2);
    const int cbase = n0c + wc * 32 + (lane & 3) * 2;
    #pragma unroll
    for (int f = 0; f < 4; f++) {
        int r = rbase + f * 16;
        #pragma unroll
        for (int g = 0; g < 4; g++) {
            int cc = cbase + g * 8;
            *(float2*)&C[(size_t)r * Kn + cc]       = make_float2(acc[f][g][0], acc[f][g][1]);
            *(float2*)&C[(size_t)(r + 8) * Kn + cc] = make_float2(acc[f][g][2], acc[f][g][3]);
        }
    }
}

// ---------------- weight pre-split ----------------
__global__ void k_split_w(const float* __restrict__ W1, const float* __restrict__ W2,
                          const float* __restrict__ W3) {
    int idx = blockIdx.x * 256 + threadIdx.x;
    int r  = idx >> 8;
    int c4 = (idx & 255) * 4;
    const float* src = (r < 1024) ? W1 + (size_t)r * Kn
                     : (r < 2048) ? W2 + (size_t)(r - 1024) * Kn
                                  : W3 + (size_t)(r - 2048) * Kn;
    float4 v = *(const float4*)&src[c4];
    hi_store(v, (char*)&g_Wh[(size_t)r * Kn + c4]);
}

// ================= l_all: fused softmax + warp-specialized tensor cores ============
// 2-term: p in bf16-hi only (pH); cap keeps hi+lo. M1 = pH*cH + pH*cL.
#define LPROW      56
#define L_OFF_PH   0                        // 336*56*2 = 37632
#define L_OFF_CH   37632                    // 2 bufs x 7168
#define L_OFF_CL   51968                    // 2 bufs x 7168
#define L_OFF_IMG  66304                    // 2 bufs x 9216
#define L_OFF_M1   84736                    // 336*72*4 = 96768 (pRaw alias: 62208)
#define L_OFF_MX   181504                   // invs[9]
#define LALL_SMEM  181632

__global__ void __launch_bounds__(512, 1)
k_lall_tc(const float* __restrict__ img, const float* __restrict__ cap,
          const int* __restrict__ lens) {
    extern __shared__ char sm[];
    const uint32_t sb = smem_u32(sm);
    __nv_bfloat16* pH = (__nv_bfloat16*)(sm + L_OFF_PH);
    float*        M1s = (float*)(sm + L_OFF_M1);
    float*       pRaw = (float*)(sm + L_OFF_M1);
    float*       invs = (float*)(sm + L_OFF_MX);

    const int bid = blockIdx.x;           // j*Bn + b
    const int b = bid % Bn;
    const int j = bid / Bn;
    const int tid  = threadIdx.x;
    const int lane = tid & 31;
    const int wid  = tid >> 5;
    const int l15  = lane & 15;
    const int lhi  = lane >> 4;
    const int len  = lens[j];
    const int off  = g_off[j];
    const int nks  = (len + 15) >> 4;
    const float NEG = -3.402823466e38f;

    for (int e = tid; e < 324 * 48; e += 512) {
        int m = e / 48, q = e - m * 48;
        int h = m / 36, v = m - h * 36;
        float x = NEG;
        if (q < len)
            x = g_logits[(size_t)((b * Hn + h) * Vn + v) * NCOL + off + q];
        pRaw[e] = x;
    }
    __syncthreads();

    if (wid < Hn) {
        const int h = wid;
        float mx = NEG;
        for (int e = lane; e < 1728; e += 32) mx = fmaxf(mx, pRaw[h * 1728 + e]);
        #pragma unroll
        for (int o = 16; o > 0; o >>= 1) mx = fmaxf(mx, __shfl_xor_sync(0xffffffffu, mx, o));
        float s = 0.f;
        for (int e = lane; e < 1728; e += 32) {
            float x = expf(pRaw[h * 1728 + e] - mx);
            pRaw[h * 1728 + e] = x;
            s += x;
        }
        #pragma unroll
        for (int o = 16; o > 0; o >>= 1) s += __shfl_xor_sync(0xffffffffu, s, o);
        if (lane == 0) invs[h] = 1.f / s;
    }
    __syncthreads();

    // normalized p -> bf16 hi only
    for (int e = tid; e < 336 * 48; e += 512) {
        int m = e / 48, q = e - m * 48;
        float x = 0.f;
        if (m < 324) x = pRaw[m * 48 + q] * invs[m / 36];
        pH[m * LPROW + q] = __float2bfloat16(x);
    }
    {
        const int kt = tid & 63, g8 = tid >> 6;
        __nv_bfloat16* cH0 = (__nv_bfloat16*)(sm + L_OFF_CH);
        __nv_bfloat16* cL0 = (__nv_bfloat16*)(sm + L_OFF_CL);
        float*         im0 = (float*)(sm + L_OFF_IMG);
        for (int q = g8; q < 48; q += 8) {
            float x = cap[(size_t)(j * Ln + q) * Kn + kt];
            __nv_bfloat16 hi, lo; split1(x, hi, lo);
            cH0[kt * LPROW + q] = hi;
            cL0[kt * LPROW + q] = lo;
        }
        for (int v = g8; v < 36; v += 8)
            im0[v * 64 + kt] = img[(size_t)(b * Vn + v) * Kn + kt];
    }
    __syncthreads();

    for (int t = 0; t < Kn / 64; t++) {
        const int k0 = t * 64;
        const uint32_t cbuf = (uint32_t)((t & 1) * 7168);
        const uint32_t ibuf = (uint32_t)((t & 1) * 9216);

        if (wid < 14) {
            const int wn = wid & 1;
            const int wg = wid >> 1;
            float acc[3][4][4];
            #pragma unroll
            for (int i = 0; i < 3; i++)
                #pragma unroll
                for (int nt = 0; nt < 4; nt++)
                    #pragma unroll
                    for (int e = 0; e < 4; e++) acc[i][nt][e] = 0.f;

            #pragma unroll 3
            for (int ks = 0; ks < nks; ks++) {
                uint32_t bh[4][2], bl[4][2];
                #pragma unroll
                for (int p2 = 0; p2 < 2; p2++) {
                    uint32_t bo = (uint32_t)((wn * 32 + p2 * 16 + l15) * 112 + lhi * 16 + ks * 32);
                    uint32_t tt[4];
                    ldsm4(tt, sb + L_OFF_CH + cbuf + bo);
                    bh[p2*2+0][0] = tt[0]; bh[p2*2+0][1] = tt[2];
                    bh[p2*2+1][0] = tt[1]; bh[p2*2+1][1] = tt[3];
                    ldsm4(tt, sb + L_OFF_CL + cbuf + bo);
                    bl[p2*2+0][0] = tt[0]; bl[p2*2+0][1] = tt[2];
                    bl[p2*2+1][0] = tt[1]; bl[p2*2+1][1] = tt[3];
                }
                #pragma unroll
                for (int i = 0; i < 3; i++) {
                    uint32_t ao = (uint32_t)((wg * 48 + i * 16 + l15) * 112 + lhi * 16 + ks * 32);
                    uint32_t ah[4];
                    ldsm4(ah, sb + L_OFF_PH + ao);
                    #pragma unroll
                    for (int nt = 0; nt < 4; nt++) {
                        mma_bf16(acc[i][nt], ah, bh[nt]);
                        mma_bf16(acc[i][nt], ah, bl[nt]);
                    }
                }
            }
            #pragma unroll
            for (int i = 0; i < 3; i++) {
                int r = (wg * 3 + i) * 16 + (lane >> 2);
                #pragma unroll
                for (int nt = 0; nt < 4; nt++) {
                    int c = wn * 32 + nt * 8 + (lane & 3) * 2;
                    *(float2*)&M1s[r * 72 + c]       = make_float2(acc[i][nt][0], acc[i][nt][1]);
                    *(float2*)&M1s[(r + 8) * 72 + c] = make_float2(acc[i][nt][2], acc[i][nt][3]);
                }
            }
        } else if (t + 1 < Kn / 64) {
            const int lt = tid - 448;
            const int kn0 = (t + 1) * 64;
            __nv_bfloat16* cHB = (__nv_bfloat16*)(sm + L_OFF_CH + ((t + 1) & 1) * 7168);
            __nv_bfloat16* cLB = (__nv_bfloat16*)(sm + L_OFF_CL + ((t + 1) & 1) * 7168);
            float*         imB = (float*)(sm + L_OFF_IMG + ((t + 1) & 1) * 9216);
            for (int q = 0; q < 48; q++) {
                float x = cap[(size_t)(j * Ln + q) * Kn + kn0 + lt];
                __nv_bfloat16 hi, lo; split1(x, hi, lo);
                cHB[lt * LPROW + q] = hi;
                cLB[lt * LPROW + q] = lo;
            }
            for (int v = 0; v < 36; v++)
                imB[v * 64 + lt] = img[(size_t)(b * Vn + v) * Kn + kn0 + lt];
        }
        __syncthreads();

        const float* imC = (const float*)(sm + L_OFF_IMG + ibuf);
        for (int e = tid; e < Hn * 64; e += 512) {
            int h = e >> 6, kt = e & 63;
            float a = 0.f;
            #pragma unroll
            for (int v = 0; v < Vn; v++)
                a += M1s[(h * Vn + v) * 72 + kt] * imC[v * 64 + kt];
            g_lall[(size_t)(bid * Hn + h) * Kn + k0 + kt] = a;
        }
        __syncthreads();
    }
}

// ---------------- gated elementwise ----------------
__global__ void k_e1(const float* __restrict__ l1, int lda1,
                     const float* __restrict__ l2, int lda2) {
    int idx = blockIdx.x * blockDim.x + threadIdx.x;
    int m  = idx / (Kn / 4);
    int k4 = (idx % (Kn / 4)) * 4;
    float4 a = *(const float4*)&l1[(size_t)m * lda1 + k4];
    float4 c = *(const float4*)&l2[(size_t)m * lda2 + k4];
    float4 g = make_float4(a.x + tanhf(c.x), a.y + tanhf(c.y),
                           a.z + tanhf(c.z), a.w + tanhf(c.w));
    size_t off = (size_t)m * Kn + k4;
    hi_store(g, (char*)(g_Gh + off));
    hi_store(c, (char*)(g_L2h + off));
}

// gated combine + l2norm; emits next step's split G/l2, or (last) the final row sum
__global__ void __launch_bounds__(256) k_e2f(const float* __restrict__ l1, int lda1,
                                             const float* __restrict__ l2, int lda2,
                                             const float* __restrict__ b1,
                                             const float* __restrict__ b2,
                                             const float* __restrict__ b3,
                                             const float* __restrict__ l1n, int last,
                                             float* __restrict__ out) {
    const int m  = blockIdx.x;
    const int k4 = threadIdx.x * 4;
    float4 a1 = *(const float4*)&l1[(size_t)m * lda1 + k4];
    float4 a2 = *(const float4*)&l2[(size_t)m * lda2 + k4];
    float4 qv = *(const float4*)&g_Qg [(size_t)m * Kn + k4];
    float4 kv = *(const float4*)&g_Kg [(size_t)m * Kn + k4];
    float4 wv = *(const float4*)&g_W3o[(size_t)m * Kn + k4];
    float4 vb1 = *(const float4*)&b1[k4];
    float4 vb2 = *(const float4*)&b2[k4];
    float4 vb3 = *(const float4*)&b3[k4];

    float4 x;
    x.x = tanhf(a1.x) * sigmoidf_(qv.x + vb1.x) + a1.x + (wv.x + vb3.x) * sigmoidf_(kv.x + vb2.x) + a2.x;
    x.y = tanhf(a1.y) * sigmoidf_(qv.y + vb1.y) + a1.y + (wv.y + vb3.y) * sigmoidf_(kv.y + vb2.y) + a2.y;
    x.z = tanhf(a1.z) * sigmoidf_(qv.z + vb1.z) + a1.z + (wv.z + vb3.z) * sigmoidf_(kv.z + vb2.z) + a2.z;
    x.w = tanhf(a1.w) * sigmoidf_(qv.w + vb1.w) + a1.w + (wv.w + vb3.w) * sigmoidf_(kv.w + vb2.w) + a2.w;

    float ss = x.x * x.x + x.y * x.y + x.z * x.z + x.w * x.w;
    float tot = blockReduceSum256(ss);
    float inv = 1.f / (sqrtf(tot) + 1e-8f);
    float4 o = make_float4(x.x * inv, x.y * inv, x.z * inv, x.w * inv);
    size_t off = (size_t)m * Kn + k4;

    if (!last) {
        *(float4*)&g_carry[off] = o;
        hi_store(o, (char*)(g_L2h + off));
        float4 a = *(const float4*)&l1n[(size_t)m * (Hn * Kn) + k4];
        float4 g = make_float4(a.x + tanhf(o.x), a.y + tanhf(o.y),
                               a.z + tanhf(o.z), a.w + tanhf(o.w));
        hi_store(g, (char*)(g_Gh + off));
    } else {
        // fused final: out[b, j] = sum_k carry[m, k];  m = j*Bn + b
        float rs = blockReduceSum256(o.x + o.y + o.z + o.w);
        if (threadIdx.x == 0) {
            int b = m % Bn, j = m / Bn;
            out[b * NCn + j] = rs;
        }
    }
}

// ---------------- launcher ----------------
extern "C" void kernel_launch(void* const* d_in, const int* in_sizes, int n_in,
                              void* d_out, int out_size) {
    const float* img  = (const float*)d_in[0];
    const float* cap  = (const float*)d_in[1];
    const int*   lens = (const int*)  d_in[2];
    const float* hmat = (const float*)d_in[3];
    /* d_in[4] = h_bias: softmax-invariant, unused */
    const float* W1 = (const float*)d_in[5];
    const float* b1 = (const float*)d_in[6];
    const float* W2 = (const float*)d_in[7];
    const float* b2 = (const float*)d_in[8];
    const float* W3 = (const float*)d_in[9];
    const float* b3 = (const float*)d_in[10];
    float* out = (float*)d_out;

    cudaFuncSetAttribute(k_lall_tc, cudaFuncAttributeMaxDynamicSharedMemorySize, LALL_SMEM);
    cudaFuncSetAttribute(logits_gemm, cudaFuncAttributeMaxDynamicSharedMemorySize, GEMM_DSMEM);
    cudaFuncSetAttribute(gated_gemm, cudaFuncAttributeMaxDynamicSharedMemorySize, PGEMM_DSMEM);

    float *pLall, *pQ, *pKg, *pW3o, *pCar, *pLog, *pCapC;
    __nv_bfloat16 *pWh, *pGh, *pL2h;
    cudaGetSymbolAddress((void**)&pLog,  g_logits);
    cudaGetSymbolAddress((void**)&pCapC, g_capC);
    cudaGetSymbolAddress((void**)&pLall, g_lall);
    cudaGetSymbolAddress((void**)&pQ,    g_Qg);
    cudaGetSymbolAddress((void**)&pKg,   g_Kg);
    cudaGetSymbolAddress((void**)&pW3o,  g_W3o);
    cudaGetSymbolAddress((void**)&pCar,  g_carry);
    cudaGetSymbolAddress((void**)&pWh,   g_Wh);
    cudaGetSymbolAddress((void**)&pGh,   g_Gh);
    cudaGetSymbolAddress((void**)&pL2h,  g_L2h);

    k_split_w<<<3072, 256>>>(W1, W2, W3);

    // Phase 0: compaction prep
    k_prefix<<<1, 32>>>(lens);
    k_zeroC<<<NCOL, 256>>>();
    k_fillC<<<dim3(NCn, Ln), 256>>>(cap, lens);

    // Phase 1: logits GEMM over compacted active columns
    logits_gemm<<<dim3(NCOL / 128, MR / 128), 256, GEMM_DSMEM>>>(img, pCapC, pLog, hmat);

    // Phase 2: attended features l_all (fused softmax + 2-term tensor cores)
    k_lall_tc<<<NCn * Bn, 512, LALL_SMEM>>>(img, cap, lens);

    // Phase 3: 8 gated steps (1-term bf16 GEMM); final row-sum fused into last k_e2f
    k_e1<<<GMr * (Kn / 4) / 256, 256>>>(pLall, Hn * Kn, pLall + Kn, Hn * Kn);
    for (int s = 0; s < 8; s++) {
        int hs = (s == 0) ? 0 : (s + 1);
        const float* l1 = pLall + (size_t)hs * Kn;  int lda1 = Hn * Kn;
        const float* l2; int lda2;
        if (s == 0) { l2 = pLall + Kn; lda2 = Hn * Kn; }
        else        { l2 = pCar;       lda2 = Kn; }
        const float* l1n = (s < 7) ? (pLall + (size_t)(s + 2) * Kn) : pLall;

        gated_gemm<<<dim3(24, GMr / 128), 256, PGEMM_DSMEM>>>(
            pGh, pL2h, pWh, pQ, pKg, pW3o);
        k_e2f<<<GMr, 256>>>(l1, lda1, l2, lda2, b1, b2, b3, l1n, s == 7, out);
    }
}